// round 1
// baseline (speedup 1.0000x reference)
#include <cuda_runtime.h>
#include <cuda_bf16.h>

// NLL sequence loss: only the last valid timestep per batch row contributes.
//   loss = -(1/B) * sum_b inputs[b, min(T,length[b])-1, target[b]]
// 512 scattered gathers + block reduction. Single block, single kernel.

#define B_DIM 512
#define T_DIM 128
#define C_DIM 2000

__global__ __launch_bounds__(B_DIM, 1)
void nll_seq_loss_kernel(const float* __restrict__ inputs,
                         const int*   __restrict__ length,
                         const int*   __restrict__ target,
                         float*       __restrict__ out) {
    const int b = threadIdx.x;

    // Gather the single contributing log-prob for this batch row.
    int len = length[b];
    int tgt = target[b];
    int last = (len < T_DIM ? len : T_DIM) - 1;
    // 64-bit index: 512*128*2000 = 131,072,000 < 2^31, but row offset math is
    // safe in 64-bit regardless.
    long long idx = ((long long)b * T_DIM + last) * C_DIM + tgt;
    float v = inputs[idx];

    // Block reduction: warp shuffle, then smem across 16 warps.
    const int lane = b & 31;
    const int wid  = b >> 5;

    #pragma unroll
    for (int off = 16; off > 0; off >>= 1)
        v += __shfl_down_sync(0xFFFFFFFFu, v, off);

    __shared__ float warp_sums[B_DIM / 32];
    if (lane == 0) warp_sums[wid] = v;
    __syncthreads();

    if (wid == 0) {
        float s = (lane < (B_DIM / 32)) ? warp_sums[lane] : 0.0f;
        #pragma unroll
        for (int off = 8; off > 0; off >>= 1)
            s += __shfl_down_sync(0xFFFFFFFFu, s, off);
        if (lane == 0)
            out[0] = -s / (float)B_DIM;
    }
}

extern "C" void kernel_launch(void* const* d_in, const int* in_sizes, int n_in,
                              void* d_out, int out_size) {
    const float* inputs = (const float*)d_in[0];
    const int*   length = (const int*)d_in[1];
    const int*   target = (const int*)d_in[2];
    float*       out    = (float*)d_out;

    nll_seq_loss_kernel<<<1, B_DIM>>>(inputs, length, target, out);
}

// round 2
// speedup vs baseline: 1.0047x; 1.0047x over previous
#include <cuda_runtime.h>
#include <cuda_bf16.h>

// NLL sequence loss: only the last valid timestep per batch row contributes.
//   loss = -(1/B) * sum_b inputs[b, min(T,length[b])-1, target[b]]
//
// Single-warp kernel: 32 threads x 16 rows each. No __syncthreads, no smem.
// Index arrays loaded as int4 (vectorized); 16 independent gathers per
// thread overlap fully in the L1tex queue.

#define B_DIM 512
#define T_DIM 128
#define C_DIM 2000
#define ROWS_PER_THREAD 16   // B_DIM / 32

__global__ __launch_bounds__(32, 1)
void nll_seq_loss_kernel(const float* __restrict__ inputs,
                         const int*   __restrict__ length,
                         const int*   __restrict__ target,
                         float*       __restrict__ out) {
    const int t = threadIdx.x;          // 0..31
    const int base = t * ROWS_PER_THREAD;

    // Vectorized index loads: 4x int4 each for length and target.
    const int4* len4 = (const int4*)(length + base);
    const int4* tgt4 = (const int4*)(target + base);

    int len[ROWS_PER_THREAD], tgt[ROWS_PER_THREAD];
    #pragma unroll
    for (int j = 0; j < ROWS_PER_THREAD / 4; j++) {
        int4 l = len4[j];
        int4 g = tgt4[j];
        len[4*j+0] = l.x; len[4*j+1] = l.y; len[4*j+2] = l.z; len[4*j+3] = l.w;
        tgt[4*j+0] = g.x; tgt[4*j+1] = g.y; tgt[4*j+2] = g.z; tgt[4*j+3] = g.w;
    }

    // 16 independent gathers (MLP=16), then in-register accumulate.
    float v[ROWS_PER_THREAD];
    #pragma unroll
    for (int j = 0; j < ROWS_PER_THREAD; j++) {
        int last = (len[j] < T_DIM ? len[j] : T_DIM) - 1;
        int b = base + j;
        long long idx = ((long long)b * T_DIM + last) * C_DIM + tgt[j];
        v[j] = inputs[idx];
    }

    float s = 0.0f;
    #pragma unroll
    for (int j = 0; j < ROWS_PER_THREAD; j++) s += v[j];

    // Warp-level reduction; no barriers needed.
    #pragma unroll
    for (int off = 16; off > 0; off >>= 1)
        s += __shfl_down_sync(0xFFFFFFFFu, s, off);

    if (t == 0)
        out[0] = -s * (1.0f / (float)B_DIM);
}

extern "C" void kernel_launch(void* const* d_in, const int* in_sizes, int n_in,
                              void* d_out, int out_size) {
    const float* inputs = (const float*)d_in[0];
    const int*   length = (const int*)d_in[1];
    const int*   target = (const int*)d_in[2];
    float*       out    = (float*)d_out;

    nll_seq_loss_kernel<<<1, 32>>>(inputs, length, target, out);
}